// round 13
// baseline (speedup 1.0000x reference)
#include <cuda_runtime.h>
#include <cuda_bf16.h>

// Problem constants
#define Bn 4
#define Hn 480
#define Wn 640
#define HWn (Hn * Wn)          // 307200
#define PWn (Wn + 2)           // 642
#define PHn (Hn + 2)           // 482
#define PHWn (PHn * PWn)       // 309444
#define PROP_TIME 18
#define TAIL 704

// Tiling
#define TILE_W 128
#define TILE_H 8
#define HALO 9
#define RX (TILE_W + 2 * HALO)   // 146
#define RY (TILE_H + 2 * HALO)   // 26
#define SSTR 147                 // smem row stride; gcd(147,32)=1

// OOB sentinel tap: yoff=481 (zero border row), xoff=0.
#define SENT_Y (PHn - 1)

// Static scratch: single ping-pong padded feature buffers g = f*conf_eff.
__device__ float g_bufA[Bn * PHWn + TAIL];
__device__ float g_bufB[Bn * PHWn + TAIL];
// Packed taps, layout [b][tap][pix], 8 B each:
//   w0: yoff(9) | xoff(10)<<9 | wxq(13)<<19
//   w1: wyq(13) | affq(signed 19)<<13
__device__ unsigned long long g_taps[(size_t)Bn * 8 * HWn];
// Fused fix/conf: q<0 -> fixed value -q; q>=0 -> conf=q.
__device__ float g_q[Bn * HWn];

// evict_last via createpolicy + cache_hint (scalar evict_last qualifier is
// rejected by ptxas on sm_103a; the cache_hint form is the supported path).
__device__ __forceinline__ unsigned long long el_policy()
{
    unsigned long long pol;
    asm("createpolicy.fractional.L2::evict_last.b64 %0, 1.0;" : "=l"(pol));
    return pol;
}
__device__ __forceinline__ unsigned long long ldg_el64(const unsigned long long* p,
                                                       unsigned long long pol)
{
    unsigned long long v;
    asm("ld.global.nc.L2::cache_hint.b64 %0, [%1], %2;"
        : "=l"(v) : "l"(p), "l"(pol));
    return v;
}
__device__ __forceinline__ float ldg_el32(const float* p, unsigned long long pol)
{
    float v;
    asm("ld.global.nc.L2::cache_hint.f32 %0, [%1], %2;"
        : "=f"(v) : "l"(p), "l"(pol));
    return v;
}

// ---------------------------------------------------------------------------
// Precompute (idempotent; replayed each graph launch).
// ---------------------------------------------------------------------------
__global__ __launch_bounds__(256)
void prep_kernel(const float* __restrict__ feat_init,
                 const float* __restrict__ guid,
                 const float* __restrict__ conf,
                 const float* __restrict__ fix,
                 const float* __restrict__ scale_ptr)
{
    int idx = blockIdx.x * blockDim.x + threadIdx.x;
    if (idx >= Bn * PHWn + TAIL) return;

    int b = idx / PHWn;
    int r = idx - b * PHWn;
    int yy = r / PWn;
    int xx = r - yy * PWn;

    bool is_tail = (idx >= Bn * PHWn);
    if (is_tail || yy == 0 || yy == PHn - 1 || xx == 0 || xx == PWn - 1) {
        g_bufA[idx] = 0.0f;
        g_bufB[idx] = 0.0f;
        return;
    }

    int y = yy - 1, x = xx - 1;
    int pix = y * Wn + x;

    // Affinity normalization (guidance channels 16..23)
    float scale = scale_ptr[0] + 1e-8f;
    float inv_scale = 1.0f / scale;
    const float* gbase = guid + ((size_t)b * 24) * HWn + pix;
    float a[8];
    float s = 1e-4f;
#pragma unroll
    for (int k = 0; k < 8; k++) {
        float v = tanhf(gbase[(16 + k) * HWn]) * inv_scale;
        a[k] = v;
        s += fabsf(v);
    }
    s = fmaxf(s, 1.0f);
    float invs = 1.0f / s;

#pragma unroll
    for (int t = 0; t < 8; t++) {
        const int kt = (t < 4) ? t : t + 1;
        const float ky = (float)(kt / 3 - 1);
        const float kx = (float)(kt % 3 - 1);

        float dy = gbase[(2 * t) * HWn];
        float dx = gbase[(2 * t + 1) * HWn];

        float py = (float)y + ky + dy;
        float px = (float)x + kx + dx;
        float y0f = floorf(py);
        float x0f = floorf(px);
        int iy = (int)y0f;
        int ix = (int)x0f;
        float wy = py - y0f;
        float wx = px - x0f;

        bool valid = (iy >= -1) & (iy <= Hn - 1) & (ix >= -1) & (ix <= Wn - 1);
        int yoff = valid ? (iy + 1) : SENT_Y;
        int xoff = valid ? (ix + 1) : 0;

        int wxq = min((int)(wx * 8192.0f + 0.5f), 8191);
        int wyq = min((int)(wy * 8192.0f + 0.5f), 8191);
        int affq = (int)rintf(a[t] * invs * 131072.0f);

        unsigned int w0 = (unsigned int)yoff | ((unsigned int)xoff << 9)
                        | ((unsigned int)wxq << 19);
        unsigned int w1 = (unsigned int)wyq | ((unsigned int)affq << 13);
        g_taps[(size_t)(b * 8 + t) * HWn + pix] =
            ((unsigned long long)w1 << 32) | w0;
    }

    int gidx = b * HWn + pix;
    float fv = fix[gidx];
    bool m = fv > 0.0f;
    float cf = conf[gidx];
    float f0 = m ? fv : feat_init[gidx];
    float ce = m ? 1.0f : cf;
    g_bufA[idx] = f0 * ce;
    g_q[gidx] = m ? -fv : cf;
}

// ---------------------------------------------------------------------------
// One propagation step: SMEM-staged tile gather with rare global fallback.
// ---------------------------------------------------------------------------
__global__ __launch_bounds__(256)
void iter_kernel(float* __restrict__ outF, int srcIsA, int write_out)
{
    __shared__ float sm[RY * SSTR];

    int tid = threadIdx.x;
    int b   = blockIdx.z;
    int tx0 = blockIdx.x * TILE_W;
    int ty0 = blockIdx.y * TILE_H;

    const float* __restrict__ gIn  = (srcIsA ? g_bufA : g_bufB) + (size_t)b * PHWn;
    float* __restrict__       gOut = (srcIsA ? g_bufB : g_bufA) + (size_t)b * PHWn;

    const unsigned long long pol = el_policy();

    const int by0 = ty0 + 1 - HALO;
    const int bx0 = tx0 + 1 - HALO;

    // Stage region (zero outside padded buffer).
    for (int i = tid; i < RY * RX; i += 256) {
        int row = i / RX;
        int col = i - row * RX;
        int gy = by0 + row;
        int gx = bx0 + col;
        float v = 0.0f;
        if ((unsigned)gy < (unsigned)PHn && (unsigned)gx < (unsigned)PWn)
            v = gIn[gy * PWn + gx];
        sm[row * SSTR + col] = v;
    }
    __syncthreads();

#pragma unroll
    for (int k = 0; k < (TILE_W * TILE_H) / 256; k++) {
        int pixt = tid + k * 256;
        int row = pixt >> 7;            // TILE_W = 128
        int col = pixt & 127;
        int y = ty0 + row;
        int x = tx0 + col;
        int r = y * Wn + x;
        int gidx = b * HWn + r;

        const unsigned long long* tp = g_taps + (size_t)(b * 8) * HWn + r;

        float acc = 0.0f;
        float asum = 0.0f;

#pragma unroll
        for (int t = 0; t < 8; t++) {
            unsigned long long w = ldg_el64(tp + (size_t)t * HWn, pol);
            unsigned int w0 = (unsigned int)w;
            unsigned int w1 = (unsigned int)(w >> 32);
            int yoff = (int)(w0 & 511u);
            int xoff = (int)((w0 >> 9) & 1023u);
            float wx = (float)(w0 >> 19) * (1.0f / 8192.0f);
            float wy = (float)(w1 & 8191u) * (1.0f / 8192.0f);
            float av = (float)(((int)w1) >> 13) * (1.0f / 131072.0f);

            int ly = yoff - by0;
            int lx = xoff - bx0;
            float v00, v01, v10, v11;
            if ((unsigned)ly < (unsigned)(RY - 1) &&
                (unsigned)lx < (unsigned)(RX - 1)) {
                int s = ly * SSTR + lx;
                v00 = sm[s];
                v01 = sm[s + 1];
                v10 = sm[s + SSTR];
                v11 = sm[s + SSTR + 1];
            } else {
                const float* p = gIn + yoff * PWn + xoff;
                v00 = p[0];
                v01 = p[1];
                v10 = p[PWn];
                v11 = p[PWn + 1];
            }
            float top = fmaf(wx, v01 - v00, v00);
            float bot = fmaf(wx, v11 - v10, v10);
            float v = fmaf(wy, bot - top, top);
            acc = fmaf(av, v, acc);
            asum += av;
        }

        // Center tap: exact sample from SMEM; affinity = 1 - sum(aff8).
        float c = sm[(row + HALO) * SSTR + (col + HALO)];
        acc = fmaf(1.0f - asum, c, acc);

        float qv = ldg_el32(g_q + gidx, pol);
        bool m = qv < 0.0f;
        float fn = m ? -qv : acc;

        if (write_out) {
            outF[gidx] = fn;
        } else {
            float gv = m ? fn : fn * qv;
            gOut[(y + 1) * PWn + (x + 1)] = gv;
        }
    }
}

extern "C" void kernel_launch(void* const* d_in, const int* in_sizes, int n_in,
                              void* d_out, int out_size)
{
    const float* feat_init  = (const float*)d_in[0];
    const float* guidance   = (const float*)d_in[1];
    const float* confidence = (const float*)d_in[2];
    const float* feat_fix   = (const float*)d_in[3];
    const float* aff_scale  = (const float*)d_in[4];
    float* out = (float*)d_out;

    const int threads = 256;
    const int prep_blocks = (Bn * PHWn + TAIL + threads - 1) / threads;
    prep_kernel<<<prep_blocks, threads>>>(feat_init, guidance, confidence,
                                          feat_fix, aff_scale);

    dim3 grid(Wn / TILE_W, Hn / TILE_H, Bn);   // 5 x 60 x 4
    int srcIsA = 1;
    for (int t = 0; t < PROP_TIME; t++) {
        int last = (t == PROP_TIME - 1) ? 1 : 0;
        iter_kernel<<<grid, threads>>>(out, srcIsA, last);
        srcIsA ^= 1;
    }
}